// round 13
// baseline (speedup 1.0000x reference)
#include <cuda_runtime.h>
#include <cuda_bf16.h>
#include <cstdint>

// ---------------- problem constants ----------------
#define NPTS   512            // batch N
#define TT     300            // time steps
#define FF     150            // feature dim
#define HH     100            // hidden dim
#define G4     400            // 4*H gate rows
// x layout strides (floats): x[n][c][t][v][m], C=3,V=25,M=2
#define XSTR_N 45000
#define XSTR_C 15000
#define XSTR_T 50

// ---------------- scratch (device globals; no allocs allowed) ----------------
__device__ float g_Xp[(size_t)TT * NPTS * G4];       // encoder pre-activations (+bias)
__device__ float g_Hs[(size_t)(TT - 1) * NPTS * HH]; // decoder hidden states
__device__ float g_Wt[FF * G4];                      // enc_Wih transposed [f][g]
__device__ float g_Wd[G4 * HH];                      // folded decoder recurrent matrix
__device__ float g_biase[G4];
__device__ float g_bias0[G4];
__device__ float g_biasd[G4];

// ---------------- helpers ----------------
__device__ __forceinline__ void ffma2(float2& c, const float2& a, const float2& b) {
    asm("fma.rn.f32x2 %0, %1, %2, %0;"
        : "+l"(reinterpret_cast<unsigned long long&>(c))
        : "l"(reinterpret_cast<const unsigned long long&>(a)),
          "l"(reinterpret_cast<const unsigned long long&>(b)));
}

__device__ __forceinline__ float sigm(float x) {
    return __fdividef(1.0f, 1.0f + __expf(-x));
}
__device__ __forceinline__ float tanh_(float x) {
    return __fdividef(2.0f, 1.0f + __expf(-2.0f * x)) - 1.0f;
}

// ---------------- prep 1: transpose enc_Wih, build biases ----------------
__global__ void prep_misc_kernel(const float* __restrict__ encWih,
                                 const float* __restrict__ encbih,
                                 const float* __restrict__ encbhh,
                                 const float* __restrict__ decWih,
                                 const float* __restrict__ decbih,
                                 const float* __restrict__ decbhh,
                                 const float* __restrict__ fcb) {
    const int gg  = blockIdx.x;   // gate row 0..399
    const int tid = threadIdx.x;  // 160 threads
    if (tid < FF) g_Wt[tid * G4 + gg] = encWih[gg * FF + tid];
    __shared__ float red[160];
    red[tid] = (tid < FF) ? decWih[gg * FF + tid] * fcb[tid] : 0.0f;
    __syncthreads();
    if (tid == 0) {
        float sum = 0.0f;
        for (int f = 0; f < FF; f++) sum += red[f];
        g_biase[gg] = encbih[gg] + encbhh[gg];
        float b0 = decbih[gg] + decbhh[gg];
        g_bias0[gg] = b0;
        g_biasd[gg] = b0 + sum;
    }
}

// ---------------- prep 2: Wd = dec_Whh + dec_Wih @ fc_W ----------------
__global__ void prep_wd_kernel(const float* __restrict__ decWih,
                               const float* __restrict__ decWhh,
                               const float* __restrict__ fcW) {
    const int gg = blockIdx.x;   // 0..399
    const int h  = threadIdx.x;  // 128 threads
    if (h < HH) {
        float acc = decWhh[gg * HH + h];
        for (int f = 0; f < FF; f++)
            acc += decWih[gg * FF + f] * fcW[f * HH + h];
        g_Wd[gg * HH + h] = acc;
    }
}

// ---------------- xproj: Xp[t*512+n][g] = xs[n,t,:] @ enc_Wih[g,:].T + biase[g] ----------------
// 40-row tiles, 512 threads, 2 CTAs/SM (smem 90.4KB). Single W buffer,
// register-prefetched (2 bars per 25-k chunk).
// Active threads 500: gi = tid%25 (gate pair base), ni = tid/25 (2 rows each).
#define XP_NT    40
#define XP_NTP   42            // even pad -> float4-aligned A loads
#define XP_KC    25
#define XP_NCH   6
#define XP_CHF   (XP_KC * G4)  // floats per chunk = 10000
#define XP_SMEM  (150 * XP_NTP * 8 + XP_CHF * 4)  // 50400 + 40000 = 90400 B

__global__ void __launch_bounds__(512, 2) xproj_kernel(const float* __restrict__ x) {
    extern __shared__ float sm[];
    float2* Adup = reinterpret_cast<float2*>(sm);        // [150][XP_NTP] (value duplicated)
    float*  Wbuf = sm + 150 * XP_NTP * 2;                // [XP_CHF]

    const int tid = threadIdx.x;
    const int nt0 = blockIdx.x * XP_NT;

    // stage A (x gather), duplicated into both f32x2 lanes
    for (int idx = tid; idx < XP_NT * FF; idx += 512) {
        int row = idx / FF, f = idx % FF;
        int nt = nt0 + row;
        int n = nt & 511, t = nt >> 9;
        float v = x[(size_t)n * XSTR_N + (f / 50) * XSTR_C + t * XSTR_T + (f % 50)];
        Adup[f * XP_NTP + row] = make_float2(v, v);
    }
    // stage W chunk 0
    {
        const float4* src = reinterpret_cast<const float4*>(g_Wt);
        float4* dst = reinterpret_cast<float4*>(Wbuf);
        #pragma unroll
        for (int i2 = 0; i2 < 5; i2++) {
            int idx = tid + i2 * 512;
            if (idx < XP_CHF / 4) dst[idx] = src[idx];
        }
    }
    __syncthreads();

    const bool act = tid < 500;
    const int gi = tid % 25;   // g-pair base: g = 2*gi + 50*j
    const int ni = tid / 25;   // rows ni*2, ni*2+1  (ni 0..19 active)

    float2 acc[2][8];
    #pragma unroll
    for (int r = 0; r < 2; r++)
        #pragma unroll
        for (int j = 0; j < 8; j++) acc[r][j] = make_float2(0.f, 0.f);

    for (int c = 0; c < XP_NCH; c++) {
        // prefetch next chunk into registers (latency hidden under compute)
        float4 pf[5];
        const bool has = (c + 1 < XP_NCH);
        if (has) {
            const float4* src = reinterpret_cast<const float4*>(g_Wt + (c + 1) * XP_CHF);
            #pragma unroll
            for (int i2 = 0; i2 < 5; i2++) {
                int idx = tid + i2 * 512;
                pf[i2] = (idx < XP_CHF / 4) ? src[idx] : make_float4(0.f, 0.f, 0.f, 0.f);
            }
        }
        if (act) {
            #pragma unroll
            for (int k = 0; k < XP_KC; k++) {
                const float4 a01 = *reinterpret_cast<const float4*>(
                    &Adup[(c * XP_KC + k) * XP_NTP + ni * 2]);
                float2 a0 = make_float2(a01.x, a01.y);
                float2 a1 = make_float2(a01.z, a01.w);
                #pragma unroll
                for (int j = 0; j < 8; j++) {
                    float2 w = *reinterpret_cast<const float2*>(&Wbuf[k * G4 + 2 * gi + 50 * j]);
                    ffma2(acc[0][j], a0, w);
                    ffma2(acc[1][j], a1, w);
                }
            }
        }
        __syncthreads();            // everyone done reading Wbuf
        if (has) {
            float4* dst = reinterpret_cast<float4*>(Wbuf);
            #pragma unroll
            for (int i2 = 0; i2 < 5; i2++) {
                int idx = tid + i2 * 512;
                if (idx < XP_CHF / 4) dst[idx] = pf[i2];
            }
        }
        __syncthreads();            // next chunk staged
    }

    if (act) {
        #pragma unroll
        for (int r = 0; r < 2; r++) {
            size_t base = (size_t)(nt0 + ni * 2 + r) * G4;
            #pragma unroll
            for (int j = 0; j < 8; j++) {
                int gg = 2 * gi + 50 * j;
                float2 o = acc[r][j];
                o.x += g_biase[gg];
                o.y += g_biase[gg + 1];
                *reinterpret_cast<float2*>(&g_Xp[base + gg]) = o;
            }
        }
    }
}

// ---------------- recurrence: 128 CTAs x 4 samples, 599 serial steps ----------------
// Shuffle-free two-phase step (proven ~equal-best structure):
//  Phase A (800 thr): thread (gate, khalf) computes half-dots for 4 samples
//    (W half-row in 13 float4 regs, h via LDS.128), STS raw partials to Psm.
//  Phase B (400 thr): thread (j, s) reads both khalf partials of its 4 gates
//    (4x LDS.64), adds x/bias, activations, c update (register), h to Hsm.
__global__ void __launch_bounds__(800, 1) recur_kernel(const float* __restrict__ encWhh,
                                                       const float* __restrict__ decWhh) {
    __shared__ __align__(16) float Hsm[4][104];   // pad [100..104) = 0
    __shared__ float Psm[4 * G4 * 2];             // [s][gate][khalf]

    const int tid   = threadIdx.x;       // 0..799
    const int gate  = tid >> 1;          // 0..399
    const int khalf = tid & 1;
    const int b0    = khalf * 13;        // k4-block base
    const int n0    = blockIdx.x * 4;
    const bool bthr = tid < G4;
    const int j  = tid % 100;            // phase-B hidden unit
    const int sB = (tid < G4) ? (tid / 100) : 0; // phase-B sample

    float4 W4[13];
    float creg = 0.0f;
    float px0 = 0.f, px1 = 0.f, px2 = 0.f, px3 = 0.f;

    // init Hsm = 0 (incl pad)
    if (tid < 416) reinterpret_cast<float*>(Hsm)[tid] = 0.0f;

    auto load_w = [&](const float* Wrow) {
        #pragma unroll
        for (int b = 0; b < 13; b++) {
            int k0 = (b0 + b) * 4;
            if (k0 < HH)
                W4[b] = *reinterpret_cast<const float4*>(Wrow + k0);
            else
                W4[b] = make_float4(0.f, 0.f, 0.f, 0.f);
        }
    };

    auto phaseA = [&]() {
        float2 acc[4];
        #pragma unroll
        for (int s = 0; s < 4; s++) acc[s] = make_float2(0.f, 0.f);
        #pragma unroll
        for (int b = 0; b < 13; b++) {
            float4 wv = W4[b];
            float2 wlo = make_float2(wv.x, wv.y);
            float2 whi = make_float2(wv.z, wv.w);
            const int off = (b0 + b) * 4;
            #pragma unroll
            for (int s = 0; s < 4; s++) {
                float4 h = *reinterpret_cast<const float4*>(&Hsm[s][off]);
                ffma2(acc[s], wlo, make_float2(h.x, h.y));
                ffma2(acc[s], whi, make_float2(h.z, h.w));
            }
        }
        #pragma unroll
        for (int s = 0; s < 4; s++)
            Psm[s * 800 + gate * 2 + khalf] = acc[s].x + acc[s].y;
    };

    auto phaseB = [&](float xi, float xf, float xg, float xo, bool store_h, int k) {
        const float* Pr = Psm + sB * 800;
        float2 q0 = *reinterpret_cast<const float2*>(&Pr[j * 2]);
        float2 q1 = *reinterpret_cast<const float2*>(&Pr[(100 + j) * 2]);
        float2 q2 = *reinterpret_cast<const float2*>(&Pr[(200 + j) * 2]);
        float2 q3 = *reinterpret_cast<const float2*>(&Pr[(300 + j) * 2]);
        float i_ = sigm(q0.x + q0.y + xi);
        float f_ = sigm(q1.x + q1.y + xf);
        float g_ = tanh_(q2.x + q2.y + xg);
        float o_ = sigm(q3.x + q3.y + xo);
        creg = f_ * creg + i_ * g_;
        float hn = o_ * tanh_(creg);
        Hsm[sB][j] = hn;
        if (store_h)
            g_Hs[((size_t)k * NPTS + n0 + sB) * HH + j] = hn;
    };

    load_w(encWhh + gate * HH);

    // prefetch x for t=0
    if (bthr) {
        const float* pp = g_Xp + ((size_t)0 * NPTS + n0 + sB) * G4 + j;
        px0 = pp[0]; px1 = pp[100]; px2 = pp[200]; px3 = pp[300];
    }
    __syncthreads();

    // ---- encoder: 300 steps ----
    for (int t = 0; t < TT; t++) {
        phaseA();
        __syncthreads();
        if (bthr) {
            float xi = px0, xf = px1, xg = px2, xo = px3;
            if (t + 1 < TT) {
                const float* pp = g_Xp + ((size_t)(t + 1) * NPTS + n0 + sB) * G4 + j;
                px0 = pp[0]; px1 = pp[100]; px2 = pp[200]; px3 = pp[300];
            }
            phaseB(xi, xf, xg, xo, false, 0);
        }
        __syncthreads();
    }

    // ---- decoder step 0: raw dec_Whh (inp = 0) ----
    load_w(decWhh + gate * HH);
    float bi = 0.f, bf = 0.f, bg = 0.f, bo = 0.f;
    if (bthr) {
        bi = g_bias0[j]; bf = g_bias0[100 + j];
        bg = g_bias0[200 + j]; bo = g_bias0[300 + j];
    }
    phaseA();
    __syncthreads();
    if (bthr) phaseB(bi, bf, bg, bo, true, 0);
    __syncthreads();

    // ---- decoder steps 1..298: folded Wd ----
    load_w(g_Wd + gate * HH);
    if (bthr) {
        bi = g_biasd[j]; bf = g_biasd[100 + j];
        bg = g_biasd[200 + j]; bo = g_biasd[300 + j];
    }
    for (int k = 1; k < TT - 1; k++) {
        phaseA();
        __syncthreads();
        if (bthr) phaseB(bi, bf, bg, bo, true, k);
        __syncthreads();
    }
}

// ---------------- zero out t=0 slice of the output ----------------
__global__ void zero_t0_kernel(float* __restrict__ out) {
    int idx = blockIdx.x * 256 + threadIdx.x;
    if (idx < NPTS * FF) {
        int n = idx / FF, f = idx % FF;
        out[(size_t)n * XSTR_N + (f / 50) * XSTR_C + (f % 50)] = 0.0f;
    }
}

// ---------------- fc: out[t>=1] = Hs @ fc_W.T + fc_b, scattered to (N,C,T,V,M) ----------------
// Block: 32 rows (flat d = k*512+n) x 150 f. 320 threads, 300 active:
//   rg = tid/75 (4 row-groups of 8), f = 2*(tid%75). FFMA2 paired over h.
#define FC_ROWS 32
#define FC_WPAD 102
#define FC_SMEM ((FF * FC_WPAD + FC_ROWS * HH) * 4)  // 61200 + 12800 = 74000 B

__global__ void __launch_bounds__(320, 2) fc_kernel(const float* __restrict__ fcW,
                                                    const float* __restrict__ fcb,
                                                    float* __restrict__ out) {
    extern __shared__ float sm[];
    float* fcWs = sm;                 // [150][FC_WPAD]
    float* hs   = sm + FF * FC_WPAD;  // [32][100]

    const int tid = threadIdx.x;  // 320
    const int d0  = blockIdx.x * FC_ROWS;

    for (int idx = tid; idx < FF * HH; idx += 320) {
        int f = idx / HH, h = idx % HH;
        fcWs[f * FC_WPAD + h] = fcW[idx];
    }
    for (int idx = tid; idx < FC_ROWS * HH; idx += 320) {
        int r = idx / HH, h = idx % HH;
        hs[r * HH + h] = g_Hs[(size_t)(d0 + r) * HH + h];
    }
    __syncthreads();

    if (tid < 300) {
        const int rg = tid / 75;
        const int f  = 2 * (tid % 75);
        float2 acc[2][8];
        #pragma unroll
        for (int a = 0; a < 2; a++)
            #pragma unroll
            for (int r = 0; r < 8; r++) acc[a][r] = make_float2(0.f, 0.f);

        #pragma unroll
        for (int h2 = 0; h2 < 50; h2++) {
            float2 wa = *reinterpret_cast<const float2*>(&fcWs[f * FC_WPAD + 2 * h2]);
            float2 wb = *reinterpret_cast<const float2*>(&fcWs[(f + 1) * FC_WPAD + 2 * h2]);
            #pragma unroll
            for (int r = 0; r < 8; r++) {
                float2 hv = *reinterpret_cast<const float2*>(&hs[(rg * 8 + r) * HH + 2 * h2]);
                ffma2(acc[0][r], wa, hv);
                ffma2(acc[1][r], wb, hv);
            }
        }

        float b0 = fcb[f], b1 = fcb[f + 1];
        int c = f / 50, rr = f % 50;
        #pragma unroll
        for (int r = 0; r < 8; r++) {
            int d = d0 + rg * 8 + r;
            int n = d & 511;
            int t = (d >> 9) + 1;
            float2 o = make_float2(acc[0][r].x + acc[0][r].y + b0,
                                   acc[1][r].x + acc[1][r].y + b1);
            *reinterpret_cast<float2*>(&out[(size_t)n * XSTR_N + c * XSTR_C + t * XSTR_T + rr]) = o;
        }
    }
}

// ---------------- launch ----------------
extern "C" void kernel_launch(void* const* d_in, const int* in_sizes, int n_in,
                              void* d_out, int out_size) {
    const float* x       = (const float*)d_in[0];
    const float* encWih  = (const float*)d_in[1];
    const float* encWhh  = (const float*)d_in[2];
    const float* encbih  = (const float*)d_in[3];
    const float* encbhh  = (const float*)d_in[4];
    const float* decWih  = (const float*)d_in[5];
    const float* decWhh  = (const float*)d_in[6];
    const float* decbih  = (const float*)d_in[7];
    const float* decbhh  = (const float*)d_in[8];
    const float* fcW     = (const float*)d_in[9];
    const float* fcb     = (const float*)d_in[10];
    float* out = (float*)d_out;
    (void)in_sizes; (void)n_in; (void)out_size;

    cudaFuncSetAttribute(xproj_kernel, cudaFuncAttributeMaxDynamicSharedMemorySize, XP_SMEM);
    cudaFuncSetAttribute(fc_kernel,    cudaFuncAttributeMaxDynamicSharedMemorySize, FC_SMEM);

    prep_misc_kernel<<<G4, 160>>>(encWih, encbih, encbhh, decWih, decbih, decbhh, fcb);
    prep_wd_kernel<<<G4, 128>>>(decWih, decWhh, fcW);

    xproj_kernel<<<(TT * NPTS) / XP_NT, 512, XP_SMEM>>>(x);           // 3840 blocks, 2 CTAs/SM
    recur_kernel<<<NPTS / 4, 800>>>(encWhh, decWhh);                  // 128 blocks, 1 wave
    zero_t0_kernel<<<(NPTS * FF + 255) / 256, 256>>>(out);
    fc_kernel<<<((TT - 1) * NPTS) / FC_ROWS, 320, FC_SMEM>>>(fcW, fcb, out);  // 4784 blocks
}

// round 14
// speedup vs baseline: 1.9193x; 1.9193x over previous
#include <cuda_runtime.h>
#include <cuda_bf16.h>
#include <cstdint>

// ---------------- problem constants ----------------
#define NPTS   512            // batch N
#define TT     300            // time steps
#define FF     150            // feature dim
#define HH     100            // hidden dim
#define G4     400            // 4*H gate rows
// x layout strides (floats): x[n][c][t][v][m], C=3,V=25,M=2
#define XSTR_N 45000
#define XSTR_C 15000
#define XSTR_T 50

// ---------------- scratch (device globals; no allocs allowed) ----------------
__device__ float g_Xp[(size_t)TT * NPTS * G4];       // encoder pre-activations (+bias)
__device__ float g_Hs[(size_t)(TT - 1) * NPTS * HH]; // decoder hidden states
__device__ float g_Wt[FF * G4];                      // enc_Wih transposed [f][g]
__device__ float g_Wd[G4 * HH];                      // folded decoder recurrent matrix
__device__ float g_biase[G4];
__device__ float g_bias0[G4];
__device__ float g_biasd[G4];

// ---------------- helpers ----------------
__device__ __forceinline__ void ffma2(float2& c, const float2& a, const float2& b) {
    asm("fma.rn.f32x2 %0, %1, %2, %0;"
        : "+l"(reinterpret_cast<unsigned long long&>(c))
        : "l"(reinterpret_cast<const unsigned long long&>(a)),
          "l"(reinterpret_cast<const unsigned long long&>(b)));
}

__device__ __forceinline__ float sigm(float x) {
    return __fdividef(1.0f, 1.0f + __expf(-x));
}
__device__ __forceinline__ float tanh_(float x) {
    return __fdividef(2.0f, 1.0f + __expf(-2.0f * x)) - 1.0f;
}

// ---------------- prep 1: transpose enc_Wih, build biases ----------------
__global__ void prep_misc_kernel(const float* __restrict__ encWih,
                                 const float* __restrict__ encbih,
                                 const float* __restrict__ encbhh,
                                 const float* __restrict__ decWih,
                                 const float* __restrict__ decbih,
                                 const float* __restrict__ decbhh,
                                 const float* __restrict__ fcb) {
    const int gg  = blockIdx.x;   // gate row 0..399
    const int tid = threadIdx.x;  // 160 threads
    if (tid < FF) g_Wt[tid * G4 + gg] = encWih[gg * FF + tid];
    __shared__ float red[160];
    red[tid] = (tid < FF) ? decWih[gg * FF + tid] * fcb[tid] : 0.0f;
    __syncthreads();
    if (tid == 0) {
        float sum = 0.0f;
        for (int f = 0; f < FF; f++) sum += red[f];
        g_biase[gg] = encbih[gg] + encbhh[gg];
        float b0 = decbih[gg] + decbhh[gg];
        g_bias0[gg] = b0;
        g_biasd[gg] = b0 + sum;
    }
}

// ---------------- prep 2: Wd = dec_Whh + dec_Wih @ fc_W ----------------
__global__ void prep_wd_kernel(const float* __restrict__ decWih,
                               const float* __restrict__ decWhh,
                               const float* __restrict__ fcW) {
    const int gg = blockIdx.x;   // 0..399
    const int h  = threadIdx.x;  // 128 threads
    if (h < HH) {
        float acc = decWhh[gg * HH + h];
        for (int f = 0; f < FF; f++)
            acc += decWih[gg * FF + f] * fcW[f * HH + h];
        g_Wd[gg * HH + h] = acc;
    }
}

// ---------------- xproj (PROVEN BEST: 80-row tiles, double-buffered W) ----------------
#define XP_NT    80
#define XP_NTP   82            // even pad -> float4-aligned A loads
#define XP_KC    25
#define XP_NCH   6
#define XP_CHF   (XP_KC * G4)  // floats per chunk = 10000
#define XP_SMEM  (150 * XP_NTP * 8 + 2 * XP_CHF * 4)  // 98400 + 80000 = 178400 B

__global__ void __launch_bounds__(512, 1) xproj_kernel(const float* __restrict__ x) {
    extern __shared__ float sm[];
    float2* Adup = reinterpret_cast<float2*>(sm);        // [150][XP_NTP] (value duplicated)
    float*  Wbuf = sm + 150 * XP_NTP * 2;                // [2][XP_CHF]

    const int tid = threadIdx.x;
    const int nt0 = blockIdx.x * XP_NT;

    // stage A (x gather), duplicated into both f32x2 lanes
    for (int idx = tid; idx < XP_NT * FF; idx += 512) {
        int row = idx / FF, f = idx % FF;
        int nt = nt0 + row;
        int n = nt & 511, t = nt >> 9;
        float v = x[(size_t)n * XSTR_N + (f / 50) * XSTR_C + t * XSTR_T + (f % 50)];
        Adup[f * XP_NTP + row] = make_float2(v, v);
    }
    // stage W chunk 0
    {
        const float4* src = reinterpret_cast<const float4*>(g_Wt);
        float4* dst = reinterpret_cast<float4*>(Wbuf);
        #pragma unroll
        for (int i2 = 0; i2 < 5; i2++) {
            int idx = tid + i2 * 512;
            if (idx < XP_CHF / 4) dst[idx] = src[idx];
        }
    }
    __syncthreads();

    const bool act = tid < 500;
    const int gi = tid % 25;   // g-pair base: g = 2*gi + 50*j
    const int ni = tid / 25;   // rows ni*4 .. ni*4+3  (ni 0..19 active)

    float2 acc[4][8];
    #pragma unroll
    for (int r = 0; r < 4; r++)
        #pragma unroll
        for (int j = 0; j < 8; j++) acc[r][j] = make_float2(0.f, 0.f);

    for (int c = 0; c < XP_NCH; c++) {
        // prefetch next chunk into registers (latency hidden under compute)
        float4 pf[5];
        const bool has = (c + 1 < XP_NCH);
        if (has) {
            const float4* src = reinterpret_cast<const float4*>(g_Wt + (c + 1) * XP_CHF);
            #pragma unroll
            for (int i2 = 0; i2 < 5; i2++) {
                int idx = tid + i2 * 512;
                pf[i2] = (idx < XP_CHF / 4) ? src[idx] : make_float4(0.f, 0.f, 0.f, 0.f);
            }
        }
        const float* Wc = Wbuf + (c & 1) * XP_CHF;
        if (act) {
            #pragma unroll
            for (int k = 0; k < XP_KC; k++) {
                const float4 a01 = *reinterpret_cast<const float4*>(
                    &Adup[(c * XP_KC + k) * XP_NTP + ni * 4]);
                const float4 a23 = *reinterpret_cast<const float4*>(
                    &Adup[(c * XP_KC + k) * XP_NTP + ni * 4 + 2]);
                float2 a0 = make_float2(a01.x, a01.y);
                float2 a1 = make_float2(a01.z, a01.w);
                float2 a2 = make_float2(a23.x, a23.y);
                float2 a3 = make_float2(a23.z, a23.w);
                #pragma unroll
                for (int j = 0; j < 8; j++) {
                    float2 w = *reinterpret_cast<const float2*>(&Wc[k * G4 + 2 * gi + 50 * j]);
                    ffma2(acc[0][j], a0, w);
                    ffma2(acc[1][j], a1, w);
                    ffma2(acc[2][j], a2, w);
                    ffma2(acc[3][j], a3, w);
                }
            }
        }
        if (has) {
            float4* dst = reinterpret_cast<float4*>(Wbuf + ((c + 1) & 1) * XP_CHF);
            #pragma unroll
            for (int i2 = 0; i2 < 5; i2++) {
                int idx = tid + i2 * 512;
                if (idx < XP_CHF / 4) dst[idx] = pf[i2];
            }
        }
        __syncthreads();
    }

    if (act) {
        #pragma unroll
        for (int r = 0; r < 4; r++) {
            size_t base = (size_t)(nt0 + ni * 4 + r) * G4;
            #pragma unroll
            for (int j = 0; j < 8; j++) {
                int gg = 2 * gi + 50 * j;
                float2 o = acc[r][j];
                o.x += g_biase[gg];
                o.y += g_biase[gg + 1];
                *reinterpret_cast<float2*>(&g_Xp[base + gg]) = o;
            }
        }
    }
}

// ---------------- recurrence: warp-local cell, ONE barrier per step ----------------
// Lane map: lane = uj*8 + type*2 + khalf  (uj = unit within warp, 4 units/warp).
// A warp owns ALL 8 producers (4 gate types x 2 k-halves) of its 4 hidden units,
// so the LSTM cell update is warp-local: phase A -> __syncwarp() -> phase B.
// Phase A (all 800): half-row dot (13 float4 W regs, LDS.128 h) for 4 samples,
//   STS 4 raw partials to a conflict-free warp-private Psm slab.
// Phase B (lanes 0..15): (uj,s) task: 2x LDS.128 partials, activations,
//   c update (register), h -> double-buffered Hsm (+g_Hs in decoder).
// One __syncthreads() per step publishes Hsm[p^1] to all warps.
__global__ void __launch_bounds__(800, 1) recur_kernel(const float* __restrict__ encWhh,
                                                       const float* __restrict__ decWhh) {
    __shared__ __align__(16) float Hsm[2][4][104];   // double-buffered, pad [100..104) = 0
    __shared__ __align__(16) float Psm[25 * 160];    // [w][uj(40)][s(8)][type(2)][khalf]

    const int tid   = threadIdx.x;        // 0..799
    const int w     = tid >> 5;           // 0..24
    const int l     = tid & 31;
    const int uj    = l >> 3;             // 0..3
    const int type  = (l >> 1) & 3;       // 0=i 1=f 2=g 3=o
    const int khalf = l & 1;
    const int j     = w * 4 + uj;         // hidden unit 0..99
    const int gate  = type * 100 + j;
    const int b0    = khalf * 13;
    const int n0    = blockIdx.x * 4;

    // phase-B task mapping (lanes 0..15)
    const bool bact = l < 16;
    const int ujb = l >> 2;               // 0..3
    const int sb  = l & 3;                // 0..3
    const int jb  = w * 4 + ujb;

    const int pbase = w * 160 + uj * 40 + type * 2 + khalf;   // A store base (+s*8)
    const int rbase = w * 160 + ujb * 40 + sb * 8;            // B read base

    float4 W4[13];
    float creg = 0.0f;
    float pxi = 0.f, pxf = 0.f, pxg = 0.f, pxo = 0.f;   // encoder x prefetch / decoder bias

    // init both Hsm buffers to 0 (2*4*104 = 832 floats)
    reinterpret_cast<float*>(Hsm)[tid] = 0.0f;
    if (tid < 32) reinterpret_cast<float*>(Hsm)[800 + tid] = 0.0f;

    auto load_w = [&](const float* Wrow) {
        #pragma unroll
        for (int b = 0; b < 13; b++) {
            int k0 = (b0 + b) * 4;
            if (k0 < HH)
                W4[b] = *reinterpret_cast<const float4*>(Wrow + k0);
            else
                W4[b] = make_float4(0.f, 0.f, 0.f, 0.f);
        }
    };

    int p = 0;

    auto phaseA = [&]() {
        float2 acc[4];
        #pragma unroll
        for (int s = 0; s < 4; s++) acc[s] = make_float2(0.f, 0.f);
        #pragma unroll
        for (int b = 0; b < 13; b++) {
            float4 wv = W4[b];
            float2 wlo = make_float2(wv.x, wv.y);
            float2 whi = make_float2(wv.z, wv.w);
            const int off = (b0 + b) * 4;
            #pragma unroll
            for (int s = 0; s < 4; s++) {
                float4 h = *reinterpret_cast<const float4*>(&Hsm[p][s][off]);
                ffma2(acc[s], wlo, make_float2(h.x, h.y));
                ffma2(acc[s], whi, make_float2(h.z, h.w));
            }
        }
        #pragma unroll
        for (int s = 0; s < 4; s++)
            Psm[pbase + s * 8] = acc[s].x + acc[s].y;
    };

    auto phaseB = [&](float xi, float xf, float xg, float xo, bool store_h, int k) {
        float4 qa = *reinterpret_cast<const float4*>(&Psm[rbase]);      // i0,i1,f0,f1
        float4 qb = *reinterpret_cast<const float4*>(&Psm[rbase + 4]);  // g0,g1,o0,o1
        float i_ = sigm(qa.x + qa.y + xi);
        float f_ = sigm(qa.z + qa.w + xf);
        float g_ = tanh_(qb.x + qb.y + xg);
        float o_ = sigm(qb.z + qb.w + xo);
        creg = f_ * creg + i_ * g_;
        float hn = o_ * tanh_(creg);
        Hsm[p ^ 1][sb][jb] = hn;
        if (store_h)
            g_Hs[((size_t)k * NPTS + n0 + sb) * HH + jb] = hn;
    };

    load_w(encWhh + gate * HH);

    // prefetch x for t=0 (B lanes)
    if (bact) {
        const float* pp = g_Xp + ((size_t)0 * NPTS + n0 + sb) * G4 + jb;
        pxi = pp[0]; pxf = pp[100]; pxg = pp[200]; pxo = pp[300];
    }
    __syncthreads();

    // ---- encoder: 300 steps ----
    for (int t = 0; t < TT; t++) {
        phaseA();
        __syncwarp();
        if (bact) {
            float xi = pxi, xf = pxf, xg = pxg, xo = pxo;
            if (t + 1 < TT) {
                const float* pp = g_Xp + ((size_t)(t + 1) * NPTS + n0 + sb) * G4 + jb;
                pxi = pp[0]; pxf = pp[100]; pxg = pp[200]; pxo = pp[300];
            }
            phaseB(xi, xf, xg, xo, false, 0);
        }
        __syncthreads();
        p ^= 1;
    }

    // ---- decoder step 0: raw dec_Whh (inp = 0) ----
    load_w(decWhh + gate * HH);
    if (bact) {
        pxi = g_bias0[jb];       pxf = g_bias0[100 + jb];
        pxg = g_bias0[200 + jb]; pxo = g_bias0[300 + jb];
    }
    phaseA();
    __syncwarp();
    if (bact) phaseB(pxi, pxf, pxg, pxo, true, 0);
    __syncthreads();
    p ^= 1;

    // ---- decoder steps 1..298: folded Wd ----
    load_w(g_Wd + gate * HH);
    if (bact) {
        pxi = g_biasd[jb];       pxf = g_biasd[100 + jb];
        pxg = g_biasd[200 + jb]; pxo = g_biasd[300 + jb];
    }
    for (int k = 1; k < TT - 1; k++) {
        phaseA();
        __syncwarp();
        if (bact) phaseB(pxi, pxf, pxg, pxo, true, k);
        __syncthreads();
        p ^= 1;
    }
}

// ---------------- zero out t=0 slice of the output ----------------
__global__ void zero_t0_kernel(float* __restrict__ out) {
    int idx = blockIdx.x * 256 + threadIdx.x;
    if (idx < NPTS * FF) {
        int n = idx / FF, f = idx % FF;
        out[(size_t)n * XSTR_N + (f / 50) * XSTR_C + (f % 50)] = 0.0f;
    }
}

// ---------------- fc (PROVEN: 32 rows, 320 threads, 2 CTAs/SM) ----------------
#define FC_ROWS 32
#define FC_WPAD 102
#define FC_SMEM ((FF * FC_WPAD + FC_ROWS * HH) * 4)  // 61200 + 12800 = 74000 B

__global__ void __launch_bounds__(320, 2) fc_kernel(const float* __restrict__ fcW,
                                                    const float* __restrict__ fcb,
                                                    float* __restrict__ out) {
    extern __shared__ float sm[];
    float* fcWs = sm;                 // [150][FC_WPAD]
    float* hs   = sm + FF * FC_WPAD;  // [32][100]

    const int tid = threadIdx.x;  // 320
    const int d0  = blockIdx.x * FC_ROWS;

    for (int idx = tid; idx < FF * HH; idx += 320) {
        int f = idx / HH, h = idx % HH;
        fcWs[f * FC_WPAD + h] = fcW[idx];
    }
    for (int idx = tid; idx < FC_ROWS * HH; idx += 320) {
        int r = idx / HH, h = idx % HH;
        hs[r * HH + h] = g_Hs[(size_t)(d0 + r) * HH + h];
    }
    __syncthreads();

    if (tid < 300) {
        const int rg = tid / 75;
        const int f  = 2 * (tid % 75);
        float2 acc[2][8];
        #pragma unroll
        for (int a = 0; a < 2; a++)
            #pragma unroll
            for (int r = 0; r < 8; r++) acc[a][r] = make_float2(0.f, 0.f);

        #pragma unroll
        for (int h2 = 0; h2 < 50; h2++) {
            float2 wa = *reinterpret_cast<const float2*>(&fcWs[f * FC_WPAD + 2 * h2]);
            float2 wb = *reinterpret_cast<const float2*>(&fcWs[(f + 1) * FC_WPAD + 2 * h2]);
            #pragma unroll
            for (int r = 0; r < 8; r++) {
                float2 hv = *reinterpret_cast<const float2*>(&hs[(rg * 8 + r) * HH + 2 * h2]);
                ffma2(acc[0][r], wa, hv);
                ffma2(acc[1][r], wb, hv);
            }
        }

        float b0 = fcb[f], b1 = fcb[f + 1];
        int c = f / 50, rr = f % 50;
        #pragma unroll
        for (int r = 0; r < 8; r++) {
            int d = d0 + rg * 8 + r;
            int n = d & 511;
            int t = (d >> 9) + 1;
            float2 o = make_float2(acc[0][r].x + acc[0][r].y + b0,
                                   acc[1][r].x + acc[1][r].y + b1);
            *reinterpret_cast<float2*>(&out[(size_t)n * XSTR_N + c * XSTR_C + t * XSTR_T + rr]) = o;
        }
    }
}

// ---------------- launch ----------------
extern "C" void kernel_launch(void* const* d_in, const int* in_sizes, int n_in,
                              void* d_out, int out_size) {
    const float* x       = (const float*)d_in[0];
    const float* encWih  = (const float*)d_in[1];
    const float* encWhh  = (const float*)d_in[2];
    const float* encbih  = (const float*)d_in[3];
    const float* encbhh  = (const float*)d_in[4];
    const float* decWih  = (const float*)d_in[5];
    const float* decWhh  = (const float*)d_in[6];
    const float* decbih  = (const float*)d_in[7];
    const float* decbhh  = (const float*)d_in[8];
    const float* fcW     = (const float*)d_in[9];
    const float* fcb     = (const float*)d_in[10];
    float* out = (float*)d_out;
    (void)in_sizes; (void)n_in; (void)out_size;

    cudaFuncSetAttribute(xproj_kernel, cudaFuncAttributeMaxDynamicSharedMemorySize, XP_SMEM);
    cudaFuncSetAttribute(fc_kernel,    cudaFuncAttributeMaxDynamicSharedMemorySize, FC_SMEM);

    prep_misc_kernel<<<G4, 160>>>(encWih, encbih, encbhh, decWih, decbih, decbhh, fcb);
    prep_wd_kernel<<<G4, 128>>>(decWih, decWhh, fcW);

    xproj_kernel<<<(TT * NPTS) / XP_NT, 512, XP_SMEM>>>(x);           // 1920 blocks
    recur_kernel<<<NPTS / 4, 800>>>(encWhh, decWhh);                  // 128 blocks, 1 wave
    zero_t0_kernel<<<(NPTS * FF + 255) / 256, 256>>>(out);
    fc_kernel<<<((TT - 1) * NPTS) / FC_ROWS, 320, FC_SMEM>>>(fcW, fcb, out);  // 4784 blocks
}